// round 1
// baseline (speedup 1.0000x reference)
#include <cuda_runtime.h>
#include <math.h>

#define Bq   8
#define Hq   8
#define Lq   2048
#define Dq   64
#define Uq   40
#define BH   64
#define CTXN (BH*Uq*Dq)
#define NCH  8

// scratch (no allocations allowed)
__device__ float g_M[BH*Lq];
__device__ int   g_top[BH*Uq];
__device__ float g_part[NCH*CTXN];

// ---------------------------------------------------------------------------
// Kernel 1: M[bh,l] = max_s(q·k[idx]) - sum_s(q·k[idx]) / L   (warp per (bh,l))
// ---------------------------------------------------------------------------
__global__ void k_M(const float* __restrict__ q, const float* __restrict__ kk,
                    const int* __restrict__ idx) {
    int gw   = (blockIdx.x * blockDim.x + threadIdx.x) >> 5;   // bh*Lq + l
    int lane = threadIdx.x & 31;
    int bh = gw >> 11;
    int l  = gw & (Lq - 1);

    const float2 qv = *((const float2*)(q + ((size_t)bh*Lq + l)*Dq) + lane);
    const float* kbase = kk + (size_t)bh*Lq*Dq;

    int jA = __ldg(idx + l*Uq + lane);
    int jB = (lane < (Uq - 32)) ? __ldg(idx + l*Uq + 32 + lane) : 0;

    float mx = -INFINITY, sm = 0.f;

    #pragma unroll 4
    for (int s = 0; s < 32; ++s) {
        int j = __shfl_sync(0xffffffffu, jA, s);
        float2 kv = __ldg((const float2*)(kbase + (size_t)j*Dq) + lane);
        float p = qv.x*kv.x + qv.y*kv.y;
        #pragma unroll
        for (int o = 16; o > 0; o >>= 1) p += __shfl_xor_sync(0xffffffffu, p, o);
        mx = fmaxf(mx, p); sm += p;
    }
    #pragma unroll
    for (int s = 0; s < (Uq - 32); ++s) {
        int j = __shfl_sync(0xffffffffu, jB, s);
        float2 kv = __ldg((const float2*)(kbase + (size_t)j*Dq) + lane);
        float p = qv.x*kv.x + qv.y*kv.y;
        #pragma unroll
        for (int o = 16; o > 0; o >>= 1) p += __shfl_xor_sync(0xffffffffu, p, o);
        mx = fmaxf(mx, p); sm += p;
    }

    if (lane == 0) g_M[gw] = mx - sm * (1.0f / (float)Lq);
}

// ---------------------------------------------------------------------------
// Kernel 2: top-40 of M per (bh), descending, ties -> lower index (jax order)
// ---------------------------------------------------------------------------
__global__ void k_topk() {
    __shared__ float sv[Lq];
    __shared__ float rv[256];
    __shared__ int   ri[256];
    int bh = blockIdx.x, t = threadIdx.x;

    for (int i = t; i < Lq; i += 256) sv[i] = g_M[bh*Lq + i];
    __syncthreads();

    for (int r = 0; r < Uq; ++r) {
        float bv = -INFINITY; int bi = Lq;
        for (int i = t; i < Lq; i += 256) {
            float x = sv[i];
            if (x > bv || (x == bv && i < bi)) { bv = x; bi = i; }
        }
        rv[t] = bv; ri[t] = bi;
        __syncthreads();
        for (int o = 128; o > 0; o >>= 1) {
            if (t < o) {
                float x = rv[t+o]; int j = ri[t+o];
                if (x > rv[t] || (x == rv[t] && j < ri[t])) { rv[t] = x; ri[t] = j; }
            }
            __syncthreads();
        }
        if (t == 0) { g_top[bh*Uq + r] = ri[0]; sv[ri[0]] = -INFINITY; }
        __syncthreads();
    }
}

// ---------------------------------------------------------------------------
// Kernel 3: raw scaled scores -> attn buffer.  Block = (bh, 128-key tile).
// ---------------------------------------------------------------------------
__global__ void k_scores(const float* __restrict__ q, const float* __restrict__ kk,
                         float* __restrict__ attn) {
    __shared__ float4 qs[Uq][16];    // 40 x 64 f32
    __shared__ float4 ks[128][17];   // 128 x 64 f32, padded (68 words) -> conflict-free
    int bh = blockIdx.y, tile = blockIdx.x, t = threadIdx.x;

    const float* qb = q  + (size_t)bh*Lq*Dq;
    const float* kb = kk + ((size_t)bh*Lq + tile*128)*Dq;

    for (int i = t; i < Uq*Dq; i += 256) {
        int r = i >> 6, d = i & 63;
        ((float*)&qs[r][0])[d] = qb[(size_t)g_top[bh*Uq + r]*Dq + d];
    }
    for (int i = t; i < 128*16; i += 256)
        ks[i >> 4][i & 15] = ((const float4*)kb)[i];
    __syncthreads();

    for (int p = t; p < Uq*128; p += 256) {
        int i = p >> 7, l = p & 127;
        float acc = 0.f;
        #pragma unroll
        for (int c = 0; c < 16; ++c) {
            float4 a = qs[i][c], b = ks[l][c];
            acc = fmaf(a.x, b.x, fmaf(a.y, b.y, fmaf(a.z, b.z, fmaf(a.w, b.w, acc))));
        }
        attn[((size_t)bh*Uq + i)*Lq + tile*128 + l] = acc * 0.125f;  // 1/sqrt(64)
    }
}

// ---------------------------------------------------------------------------
// Kernel 4: row softmax in-place on attn (block per row)
// ---------------------------------------------------------------------------
__global__ void k_softmax(float* __restrict__ attn) {
    __shared__ float red[256];
    int row = blockIdx.x, t = threadIdx.x;
    float* a = attn + (size_t)row * Lq;

    float4 v0 = ((float4*)a)[t];
    float4 v1 = ((float4*)a)[t + 256];

    float mx = fmaxf(fmaxf(fmaxf(v0.x, v0.y), fmaxf(v0.z, v0.w)),
                     fmaxf(fmaxf(v1.x, v1.y), fmaxf(v1.z, v1.w)));
    red[t] = mx; __syncthreads();
    for (int o = 128; o > 0; o >>= 1) { if (t < o) red[t] = fmaxf(red[t], red[t+o]); __syncthreads(); }
    mx = red[0]; __syncthreads();

    v0.x = expf(v0.x - mx); v0.y = expf(v0.y - mx);
    v0.z = expf(v0.z - mx); v0.w = expf(v0.w - mx);
    v1.x = expf(v1.x - mx); v1.y = expf(v1.y - mx);
    v1.z = expf(v1.z - mx); v1.w = expf(v1.w - mx);

    float s = v0.x + v0.y + v0.z + v0.w + v1.x + v1.y + v1.z + v1.w;
    red[t] = s; __syncthreads();
    for (int o = 128; o > 0; o >>= 1) { if (t < o) red[t] += red[t+o]; __syncthreads(); }
    float inv = 1.0f / red[0];

    v0.x *= inv; v0.y *= inv; v0.z *= inv; v0.w *= inv;
    v1.x *= inv; v1.y *= inv; v1.z *= inv; v1.w *= inv;
    ((float4*)a)[t]       = v0;
    ((float4*)a)[t + 256] = v1;
}

// ---------------------------------------------------------------------------
// Kernel 5: partial context = attn(chunk) @ V(chunk).  Block = (chunk, bh).
// Deterministic split-K over 8 l-chunks of 256.
// ---------------------------------------------------------------------------
__global__ void k_ctx(const float* __restrict__ v, const float* __restrict__ attn) {
    __shared__ float4 vs[64][17];   // 64 x 64 f32, padded
    __shared__ float  as[Uq][64];   // 40 x 64 attn tile
    int bh = blockIdx.y, ch = blockIdx.x, t = threadIdx.x;
    int d = t & 63, ig = t >> 6;    // ig in 0..7

    float acc[5] = {0.f, 0.f, 0.f, 0.f, 0.f};

    for (int tl = 0; tl < 4; ++tl) {
        int l0 = ch*256 + tl*64;
        for (int i = t; i < 64*16; i += 512)
            vs[i >> 4][i & 15] = ((const float4*)(v + ((size_t)bh*Lq + l0)*Dq))[i];
        for (int i = t; i < Uq*64; i += 512)
            as[i >> 6][i & 63] = attn[((size_t)bh*Uq + (i >> 6))*Lq + l0 + (i & 63)];
        __syncthreads();

        #pragma unroll 4
        for (int l = 0; l < 64; ++l) {
            float vv = ((const float*)&vs[l][0])[d];
            #pragma unroll
            for (int r = 0; r < 5; ++r) acc[r] += as[ig + 8*r][l] * vv;
        }
        __syncthreads();
    }
    for (int r = 0; r < 5; ++r)
        g_part[(size_t)ch*CTXN + ((size_t)bh*Uq + ig + 8*r)*Dq + d] = acc[r];
}

// ---------------------------------------------------------------------------
// Kernel 6: reduce the 8 partials (fixed order -> deterministic)
// ---------------------------------------------------------------------------
__global__ void k_reduce(float* __restrict__ ctx) {
    int i = blockIdx.x*256 + threadIdx.x;
    if (i < CTXN) {
        float s = 0.f;
        #pragma unroll
        for (int c = 0; c < NCH; ++c) s += g_part[(size_t)c*CTXN + i];
        ctx[i] = s;
    }
}

// ---------------------------------------------------------------------------
extern "C" void kernel_launch(void* const* d_in, const int* in_sizes, int n_in,
                              void* d_out, int out_size) {
    const float* q   = (const float*)d_in[0];
    const float* k   = (const float*)d_in[1];
    const float* v   = (const float*)d_in[2];
    const int*   idx = (const int*)d_in[3];

    float* ctx  = (float*)d_out;          // (B,H,u,D) = 163840 f32
    float* attn = ctx + CTXN;             // (B,H,u,L) = 5242880 f32

    k_M<<<(BH*Lq*32)/256, 256>>>(q, k, idx);
    k_topk<<<BH, 256>>>();
    k_scores<<<dim3(Lq/128, BH), 256>>>(q, k, attn);
    k_softmax<<<BH*Uq, 256>>>(attn);
    k_ctx<<<dim3(NCH, BH), 512>>>(v, attn);
    k_reduce<<<(CTXN + 255)/256, 256>>>(ctx);
}